// round 16
// baseline (speedup 1.0000x reference)
#include <cuda_runtime.h>
#include <cstdint>

#define N_NODES 100000
#define OUTW 68
typedef unsigned long long u64;
typedef unsigned int u32;

__device__ float g_nsum[(size_t)N_NODES * 64];
__device__ float g_deg[N_NODES];
__device__ unsigned g_pmaskbits[3136];
__device__ int g_list[N_NODES];
__device__ int g_cnt;

// ---------------------------------------------------------------------------
// helpers
// ---------------------------------------------------------------------------
__device__ __forceinline__ u32 pack_bf16x2(float x0, float x1) {
    u32 r;
    asm("{.reg .b16 lo, hi;\n\t"
        "cvt.rn.bf16.f32 lo, %1;\n\t"
        "cvt.rn.bf16.f32 hi, %2;\n\t"
        "mov.b32 %0, {lo, hi};}"
        : "=r"(r) : "f"(x0), "f"(x1));
    return r;
}
__device__ __forceinline__ float bf_lo_f32(u32 w) { return __uint_as_float(w << 16); }
__device__ __forceinline__ float bf_hi_f32(u32 w) { return __uint_as_float(w & 0xffff0000u); }

__device__ __forceinline__ void mma_bf16(float* c, u32 a0, u32 a1, u32 a2, u32 a3,
                                         u32 b0, u32 b1) {
    asm("mma.sync.aligned.m16n8k16.row.col.f32.bf16.bf16.f32 "
        "{%0,%1,%2,%3}, {%4,%5,%6,%7}, {%8,%9}, {%0,%1,%2,%3};"
        : "+f"(c[0]), "+f"(c[1]), "+f"(c[2]), "+f"(c[3])
        : "r"(a0), "r"(a1), "r"(a2), "r"(a3), "r"(b0), "r"(b1));
}

// ---------------------------------------------------------------------------
// Kernel 1: softmax gate -> bit mask, zero deg, zero nsum rows of gate-pass
// nodes, zero output rows of gate-fail nodes.
// ---------------------------------------------------------------------------
__global__ void pmask_kernel(const float* __restrict__ ops,
                             float* __restrict__ out) {
    int n = blockIdx.x * blockDim.x + threadIdx.x;
    if (n == 0) g_cnt = 0;
    bool msk = false;
    if (n < N_NODES) {
        float o0 = ops[n * 4 + 0], o1 = ops[n * 4 + 1];
        float o2 = ops[n * 4 + 2], o3 = ops[n * 4 + 3];
        float mx = fmaxf(fmaxf(o0, o1), fmaxf(o2, o3));
        float e0 = expf(o0 - mx), e1 = expf(o1 - mx);
        float e2 = expf(o2 - mx), e3 = expf(o3 - mx);
        float p0 = e0 / (e0 + e1 + e2 + e3);
        msk = (p0 > 0.5f);
        g_deg[n] = 0.f;
    }
    unsigned bits = __ballot_sync(0xffffffffu, msk);
    if ((threadIdx.x & 31) == 0 && (n & ~31) < N_NODES)
        g_pmaskbits[n >> 5] = bits;
    if (n < N_NODES) {
        float4 z = make_float4(0.f, 0.f, 0.f, 0.f);
        if (msk) {
            float4* row = reinterpret_cast<float4*>(g_nsum) + (size_t)n * 16;
            #pragma unroll
            for (int c = 0; c < 16; c++) row[c] = z;
        } else {
            float4* orow = reinterpret_cast<float4*>(out + (size_t)n * OUTW);
            #pragma unroll
            for (int c = 0; c < 17; c++) orow[c] = z;
        }
    }
}

// ---------------------------------------------------------------------------
// Kernel 2: gated edge scatter — one thread per edge, ballot redistribution
// ---------------------------------------------------------------------------
__device__ __forceinline__ void scatter_jobs(bool active, int tgt, int srcn,
                                             int lane,
                                             const float4* __restrict__ feat4,
                                             float4* nsum4) {
    unsigned m = __ballot_sync(0xffffffffu, active);
    int grp = lane >> 3;
    int c = lane & 7;
    while (m) {
        int b0 = -1, b1 = -1, b2 = -1, b3 = -1;
        b0 = __ffs(m) - 1; m &= m - 1;
        if (m) { b1 = __ffs(m) - 1; m &= m - 1; }
        if (m) { b2 = __ffs(m) - 1; m &= m - 1; }
        if (m) { b3 = __ffs(m) - 1; m &= m - 1; }
        int myb = (grp == 0) ? b0 : (grp == 1) ? b1 : (grp == 2) ? b2 : b3;
        int bb = (myb >= 0) ? myb : b0;
        int T = __shfl_sync(0xffffffffu, tgt,  bb);
        int S = __shfl_sync(0xffffffffu, srcn, bb);
        if (myb >= 0) {
            float4 v0 = __ldg(&feat4[(size_t)S * 16 + c]);
            float4 v1 = __ldg(&feat4[(size_t)S * 16 + c + 8]);
            asm volatile("red.global.add.v4.f32 [%0], {%1,%2,%3,%4};" ::
                         "l"(nsum4 + (size_t)T * 16 + c),
                         "f"(v0.x), "f"(v0.y), "f"(v0.z), "f"(v0.w) : "memory");
            asm volatile("red.global.add.v4.f32 [%0], {%1,%2,%3,%4};" ::
                         "l"(nsum4 + (size_t)T * 16 + c + 8),
                         "f"(v1.x), "f"(v1.y), "f"(v1.z), "f"(v1.w) : "memory");
            if (c == 0) atomicAdd(&g_deg[T], 1.f);
        }
    }
}

__global__ void edge_kernel(const int* __restrict__ ei,
                            const float4* __restrict__ feat4,
                            int E) {
    int e = blockIdx.x * blockDim.x + threadIdx.x;
    int lane = threadIdx.x & 31;
    bool v = e < E;
    int s = 0, d = 0;
    if (v) { s = __ldg(&ei[e]); d = __ldg(&ei[E + e]); }
    bool a0 = v && ((g_pmaskbits[s >> 5] >> (s & 31)) & 1);
    bool a1 = v && ((g_pmaskbits[d >> 5] >> (d & 31)) & 1);
    float4* nsum4 = reinterpret_cast<float4*>(g_nsum);
    scatter_jobs(a0, s, d, lane, feat4, nsum4);
    scatter_jobs(a1, d, s, lane, feat4, nsum4);
}

// ---------------------------------------------------------------------------
// Kernel 3: compact active nodes; zero output rows of gate-pass-but-deg0 nodes
// ---------------------------------------------------------------------------
__global__ void compact_kernel(float* __restrict__ out) {
    int n = blockIdx.x * blockDim.x + threadIdx.x;
    int lane = threadIdx.x & 31;
    bool gate = false, act = false;
    if (n < N_NODES) {
        gate = (g_pmaskbits[n >> 5] >> (n & 31)) & 1;
        act = gate && (g_deg[n] > 0.f);
    }
    unsigned m = __ballot_sync(0xffffffffu, act);
    int base = 0;
    if (lane == 0 && m) base = atomicAdd(&g_cnt, __popc(m));
    base = __shfl_sync(0xffffffffu, base, 0);
    if (act) g_list[base + __popc(m & ((1u << lane) - 1))] = n;
    if (gate && !act) {
        float4 z = make_float4(0.f, 0.f, 0.f, 0.f);
        float4* orow = reinterpret_cast<float4*>(out + (size_t)n * OUTW);
        #pragma unroll
        for (int c = 0; c < 17; c++) orow[c] = z;
    }
}

// ---------------------------------------------------------------------------
// Kernel 4: tensor-core MLP, QUAD warps; 28 warps/block = 7 quads (occ 43.75%)
// ---------------------------------------------------------------------------
#define MWARPS 28
#define QUADS  (MWARPS / 4)
#define MTHREADS (MWARPS * 32)
#define SA 132

#define OFF_W1B  0          // 8192 u64
#define OFF_W2B  16384      // 4096 u64
#define OFF_W3B  24576      // 2304 u64
#define OFF_P1B  29184      // 1024 u64
#define OFF_B1   31232
#define OFF_B2   31360
#define OFF_B3   31424      // 72
#define OFF_PB1  31496
#define OFF_P2   31528
#define OFF_PB2  31560
#define OFF_ABUF 31562
#define SMEM_FLOATS (OFF_ABUF + QUADS * 16 * SA)

__device__ void stage_wfrag(const float* __restrict__ W, u64* dst,
                            int KT, int NT, int Kv, int Nv, int ld, int tid) {
    int total = NT * KT * 64;
    for (int idx = tid; idx < total; idx += MTHREADS) {
        int gg  = idx & 7;
        int tt  = (idx >> 3) & 3;
        int reg = (idx >> 5) & 1;
        int kt  = (idx >> 6) % KT;
        int nt  = (idx >> 6) / KT;
        int k0 = kt * 16 + reg * 8 + 2 * tt;
        int n  = nt * 8 + gg;
        float w0 = (k0 < Kv && n < Nv) ? W[k0 * ld + n] : 0.f;
        float w1 = (k0 + 1 < Kv && n < Nv) ? W[(k0 + 1) * ld + n] : 0.f;
        u32 hi = pack_bf16x2(w0, w1);
        u32 lo = pack_bf16x2(w0 - bf_lo_f32(hi), w1 - bf_hi_f32(hi));
        dst[idx] = (u64)hi | ((u64)lo << 32);
    }
}

__global__ void __launch_bounds__(MTHREADS, 1)
mlp_kernel(const float* __restrict__ nf,
           const float* __restrict__ W1, const float* __restrict__ b1,
           const float* __restrict__ W2, const float* __restrict__ b2,
           const float* __restrict__ W3, const float* __restrict__ b3,
           const float* __restrict__ P1, const float* __restrict__ pb1,
           const float* __restrict__ P2, const float* __restrict__ pb2,
           float* __restrict__ out) {
    extern __shared__ float sm[];
    const int tid = threadIdx.x;

    stage_wfrag(W1, reinterpret_cast<u64*>(sm + OFF_W1B), 8, 16, 128, 128, 128, tid);
    stage_wfrag(W2, reinterpret_cast<u64*>(sm + OFF_W2B), 8,  8, 128,  64,  64, tid);
    stage_wfrag(W3, reinterpret_cast<u64*>(sm + OFF_W3B), 4,  9,  64,  67,  67, tid);
    stage_wfrag(P1, reinterpret_cast<u64*>(sm + OFF_P1B), 4,  4,  64,  32,  32, tid);
    for (int i = tid; i < 128; i += MTHREADS) sm[OFF_B1 + i] = b1[i];
    for (int i = tid; i < 64;  i += MTHREADS) sm[OFF_B2 + i] = b2[i];
    for (int i = tid; i < 72;  i += MTHREADS) sm[OFF_B3 + i] = (i < 67) ? b3[i] : 0.f;
    for (int i = tid; i < 32;  i += MTHREADS) sm[OFF_PB1 + i] = pb1[i];
    for (int i = tid; i < 32;  i += MTHREADS) sm[OFF_P2 + i] = P2[i];
    if (tid == 0) sm[OFF_PB2] = pb2[0];
    __syncthreads();

    const int warpId = tid >> 5;
    const int quadId = warpId >> 2;
    const int wiq    = warpId & 3;
    const int lane = tid & 31;
    const int tt = lane & 3;
    const int gg = lane >> 2;
    const int lane_off = tt * 8 + gg;

    #define QUAD_BAR() asm volatile("bar.sync %0, 128;" :: "r"(quadId + 1) : "memory")

    float* Abuf = sm + OFF_ABUF + quadId * (16 * SA);
    const u64* sW1 = reinterpret_cast<const u64*>(sm + OFF_W1B);
    const u64* sW2 = reinterpret_cast<const u64*>(sm + OFF_W2B);
    const u64* sW3 = reinterpret_cast<const u64*>(sm + OFF_W3B);
    const u64* sP1 = reinterpret_cast<const u64*>(sm + OFF_P1B);

    const int cnt = g_cnt;
    const int totalQuads = gridDim.x * QUADS;

    for (int grp = blockIdx.x * QUADS + quadId; grp * 16 < cnt; grp += totalQuads) {
        const int gbase = grp * 16;

        int li_lo = gbase + gg;
        int li_hi = gbase + gg + 8;
        bool v_lo = li_lo < cnt;
        bool v_hi = li_hi < cnt;
        int n1 = g_list[v_lo ? li_lo : gbase];
        int n2 = g_list[v_hi ? li_hi : gbase];

        // ---- ctx load: each warp loads 4 of the 16 rows ----
        #pragma unroll
        for (int j = 0; j < 4; j++) {
            int q = wiq * 4 + j;
            int li = gbase + q;
            int nq = g_list[(li < cnt) ? li : gbase];
            float inv = 1.f / fmaxf(g_deg[nq], 1.f);
            Abuf[q * SA + lane]      = nf[(size_t)nq * 64 + lane];
            Abuf[q * SA + 32 + lane] = nf[(size_t)nq * 64 + 32 + lane];
            Abuf[q * SA + 64 + lane] = g_nsum[(size_t)nq * 64 + lane] * inv;
            Abuf[q * SA + 96 + lane] = g_nsum[(size_t)nq * 64 + 32 + lane] * inv;
        }
        QUAD_BAR();

        // ================= layer 1: warp does nt = wiq*4 .. +3 ============
        {
            const int ntBase = wiq * 4;
            float C[4][4];
            #pragma unroll
            for (int j = 0; j < 4; j++) {
                int nt = ntBase + j;
                float bb0 = sm[OFF_B1 + nt * 8 + 2 * tt];
                float bb1 = sm[OFF_B1 + nt * 8 + 2 * tt + 1];
                C[j][0] = bb0; C[j][1] = bb1; C[j][2] = bb0; C[j][3] = bb1;
            }
            #pragma unroll
            for (int kt = 0; kt < 8; kt++) {
                float2 v0 = *reinterpret_cast<float2*>(&Abuf[gg * SA + kt * 16 + 2 * tt]);
                float2 v1 = *reinterpret_cast<float2*>(&Abuf[(gg + 8) * SA + kt * 16 + 2 * tt]);
                float2 v2 = *reinterpret_cast<float2*>(&Abuf[gg * SA + kt * 16 + 8 + 2 * tt]);
                float2 v3 = *reinterpret_cast<float2*>(&Abuf[(gg + 8) * SA + kt * 16 + 8 + 2 * tt]);
                u32 ah0 = pack_bf16x2(v0.x, v0.y), ah1 = pack_bf16x2(v1.x, v1.y);
                u32 ah2 = pack_bf16x2(v2.x, v2.y), ah3 = pack_bf16x2(v3.x, v3.y);
                u32 al0 = pack_bf16x2(v0.x - bf_lo_f32(ah0), v0.y - bf_hi_f32(ah0));
                u32 al1 = pack_bf16x2(v1.x - bf_lo_f32(ah1), v1.y - bf_hi_f32(ah1));
                u32 al2 = pack_bf16x2(v2.x - bf_lo_f32(ah2), v2.y - bf_hi_f32(ah2));
                u32 al3 = pack_bf16x2(v3.x - bf_lo_f32(ah3), v3.y - bf_hi_f32(ah3));
                #pragma unroll
                for (int j = 0; j < 4; j++) {
                    int nt = ntBase + j;
                    const u64* wb = sW1 + ((nt * 8 + kt) * 2) * 32 + lane_off;
                    u64 w0 = wb[0], w1 = wb[32];
                    u32 b0h = (u32)w0, b0l = (u32)(w0 >> 32);
                    u32 b1h = (u32)w1, b1l = (u32)(w1 >> 32);
                    mma_bf16(C[j], ah0, ah1, ah2, ah3, b0h, b1h);
                    mma_bf16(C[j], al0, al1, al2, al3, b0h, b1h);
                    mma_bf16(C[j], ah0, ah1, ah2, ah3, b0l, b1l);
                }
            }
            QUAD_BAR();   // done READING Abuf before overwrite
            #pragma unroll
            for (int j = 0; j < 4; j++) {
                int nt = ntBase + j;
                *reinterpret_cast<float2*>(&Abuf[gg * SA + nt * 8 + 2 * tt]) =
                    make_float2(fmaxf(C[j][0], 0.f), fmaxf(C[j][1], 0.f));
                *reinterpret_cast<float2*>(&Abuf[(gg + 8) * SA + nt * 8 + 2 * tt]) =
                    make_float2(fmaxf(C[j][2], 0.f), fmaxf(C[j][3], 0.f));
            }
            QUAD_BAR();
        }

        // ================= layer 2: warp does nt = wiq*2 .. +1 ============
        {
            const int ntBase = wiq * 2;
            float C[2][4];
            #pragma unroll
            for (int j = 0; j < 2; j++) {
                int nt = ntBase + j;
                float bb0 = sm[OFF_B2 + nt * 8 + 2 * tt];
                float bb1 = sm[OFF_B2 + nt * 8 + 2 * tt + 1];
                C[j][0] = bb0; C[j][1] = bb1; C[j][2] = bb0; C[j][3] = bb1;
            }
            #pragma unroll
            for (int kt = 0; kt < 8; kt++) {
                float2 v0 = *reinterpret_cast<float2*>(&Abuf[gg * SA + kt * 16 + 2 * tt]);
                float2 v1 = *reinterpret_cast<float2*>(&Abuf[(gg + 8) * SA + kt * 16 + 2 * tt]);
                float2 v2 = *reinterpret_cast<float2*>(&Abuf[gg * SA + kt * 16 + 8 + 2 * tt]);
                float2 v3 = *reinterpret_cast<float2*>(&Abuf[(gg + 8) * SA + kt * 16 + 8 + 2 * tt]);
                u32 ah0 = pack_bf16x2(v0.x, v0.y), ah1 = pack_bf16x2(v1.x, v1.y);
                u32 ah2 = pack_bf16x2(v2.x, v2.y), ah3 = pack_bf16x2(v3.x, v3.y);
                u32 al0 = pack_bf16x2(v0.x - bf_lo_f32(ah0), v0.y - bf_hi_f32(ah0));
                u32 al1 = pack_bf16x2(v1.x - bf_lo_f32(ah1), v1.y - bf_hi_f32(ah1));
                u32 al2 = pack_bf16x2(v2.x - bf_lo_f32(ah2), v2.y - bf_hi_f32(ah2));
                u32 al3 = pack_bf16x2(v3.x - bf_lo_f32(ah3), v3.y - bf_hi_f32(ah3));
                #pragma unroll
                for (int j = 0; j < 2; j++) {
                    int nt = ntBase + j;
                    const u64* wb = sW2 + ((nt * 8 + kt) * 2) * 32 + lane_off;
                    u64 w0 = wb[0], w1 = wb[32];
                    u32 b0h = (u32)w0, b0l = (u32)(w0 >> 32);
                    u32 b1h = (u32)w1, b1l = (u32)(w1 >> 32);
                    mma_bf16(C[j], ah0, ah1, ah2, ah3, b0h, b1h);
                    mma_bf16(C[j], al0, al1, al2, al3, b0h, b1h);
                    mma_bf16(C[j], ah0, ah1, ah2, ah3, b0l, b1l);
                }
            }
            QUAD_BAR();
            #pragma unroll
            for (int j = 0; j < 2; j++) {
                int nt = ntBase + j;
                *reinterpret_cast<float2*>(&Abuf[gg * SA + nt * 8 + 2 * tt]) =
                    make_float2(fmaxf(C[j][0], 0.f), fmaxf(C[j][1], 0.f));
                *reinterpret_cast<float2*>(&Abuf[(gg + 8) * SA + nt * 8 + 2 * tt]) =
                    make_float2(fmaxf(C[j][2], 0.f), fmaxf(C[j][3], 0.f));
            }
            QUAD_BAR();
        }

        // ================= layer 3: 9 nt tiles, split 3/2/2/2 ==============
        {
            const int l3base = (wiq == 0) ? 0 : (wiq == 1) ? 3 : (wiq == 2) ? 5 : 7;
            const int l3cnt  = (wiq == 0) ? 3 : 2;
            float C[3][4];
            #pragma unroll
            for (int j = 0; j < 3; j++) {
                if (j >= l3cnt) break;
                int nt = l3base + j;
                float bb0 = sm[OFF_B3 + nt * 8 + 2 * tt];
                float bb1 = sm[OFF_B3 + nt * 8 + 2 * tt + 1];
                C[j][0] = bb0; C[j][1] = bb1; C[j][2] = bb0; C[j][3] = bb1;
            }
            #pragma unroll
            for (int kt = 0; kt < 4; kt++) {
                float2 v0 = *reinterpret_cast<float2*>(&Abuf[gg * SA + kt * 16 + 2 * tt]);
                float2 v1 = *reinterpret_cast<float2*>(&Abuf[(gg + 8) * SA + kt * 16 + 2 * tt]);
                float2 v2 = *reinterpret_cast<float2*>(&Abuf[gg * SA + kt * 16 + 8 + 2 * tt]);
                float2 v3 = *reinterpret_cast<float2*>(&Abuf[(gg + 8) * SA + kt * 16 + 8 + 2 * tt]);
                u32 ah0 = pack_bf16x2(v0.x, v0.y), ah1 = pack_bf16x2(v1.x, v1.y);
                u32 ah2 = pack_bf16x2(v2.x, v2.y), ah3 = pack_bf16x2(v3.x, v3.y);
                u32 al0 = pack_bf16x2(v0.x - bf_lo_f32(ah0), v0.y - bf_hi_f32(ah0));
                u32 al1 = pack_bf16x2(v1.x - bf_lo_f32(ah1), v1.y - bf_hi_f32(ah1));
                u32 al2 = pack_bf16x2(v2.x - bf_lo_f32(ah2), v2.y - bf_hi_f32(ah2));
                u32 al3 = pack_bf16x2(v3.x - bf_lo_f32(ah3), v3.y - bf_hi_f32(ah3));
                #pragma unroll
                for (int j = 0; j < 3; j++) {
                    if (j >= l3cnt) break;
                    int nt = l3base + j;
                    const u64* wb = sW3 + ((nt * 4 + kt) * 2) * 32 + lane_off;
                    u64 w0 = wb[0], w1 = wb[32];
                    u32 b0h = (u32)w0, b0l = (u32)(w0 >> 32);
                    u32 b1h = (u32)w1, b1l = (u32)(w1 >> 32);
                    mma_bf16(C[j], ah0, ah1, ah2, ah3, b0h, b1h);
                    mma_bf16(C[j], al0, al1, al2, al3, b0h, b1h);
                    mma_bf16(C[j], ah0, ah1, ah2, ah3, b0l, b1l);
                }
            }
            QUAD_BAR();
            #pragma unroll
            for (int j = 0; j < 3; j++) {
                if (j >= l3cnt) break;
                int nt = l3base + j;
                int col = nt * 8 + 2 * tt;
                float r0 = C[j][0], r1 = C[j][1], r2 = C[j][2], r3 = C[j][3];
                if (col < 67) {
                    if (v_lo) out[(size_t)n1 * OUTW + col] = r0;
                    if (v_hi) out[(size_t)n2 * OUTW + col] = r2;
                    if (col >= 3) {
                        Abuf[gg * SA + col - 3] = r0;
                        Abuf[(gg + 8) * SA + col - 3] = r2;
                    }
                }
                if (col + 1 < 67) {
                    if (v_lo) out[(size_t)n1 * OUTW + col + 1] = r1;
                    if (v_hi) out[(size_t)n2 * OUTW + col + 1] = r3;
                    if (col + 1 >= 3) {
                        Abuf[gg * SA + col - 2] = r1;
                        Abuf[(gg + 8) * SA + col - 2] = r3;
                    }
                }
            }
            QUAD_BAR();
        }

        // ================= head (duplicated in all warps, wiq0 writes) =====
        {
            float C[4][4];
            #pragma unroll
            for (int nt = 0; nt < 4; nt++) {
                float bb0 = sm[OFF_PB1 + nt * 8 + 2 * tt];
                float bb1 = sm[OFF_PB1 + nt * 8 + 2 * tt + 1];
                C[nt][0] = bb0; C[nt][1] = bb1; C[nt][2] = bb0; C[nt][3] = bb1;
            }
            #pragma unroll
            for (int kt = 0; kt < 4; kt++) {
                float2 v0 = *reinterpret_cast<float2*>(&Abuf[gg * SA + kt * 16 + 2 * tt]);
                float2 v1 = *reinterpret_cast<float2*>(&Abuf[(gg + 8) * SA + kt * 16 + 2 * tt]);
                float2 v2 = *reinterpret_cast<float2*>(&Abuf[gg * SA + kt * 16 + 8 + 2 * tt]);
                float2 v3 = *reinterpret_cast<float2*>(&Abuf[(gg + 8) * SA + kt * 16 + 8 + 2 * tt]);
                u32 ah0 = pack_bf16x2(v0.x, v0.y), ah1 = pack_bf16x2(v1.x, v1.y);
                u32 ah2 = pack_bf16x2(v2.x, v2.y), ah3 = pack_bf16x2(v3.x, v3.y);
                u32 al0 = pack_bf16x2(v0.x - bf_lo_f32(ah0), v0.y - bf_hi_f32(ah0));
                u32 al1 = pack_bf16x2(v1.x - bf_lo_f32(ah1), v1.y - bf_hi_f32(ah1));
                u32 al2 = pack_bf16x2(v2.x - bf_lo_f32(ah2), v2.y - bf_hi_f32(ah2));
                u32 al3 = pack_bf16x2(v3.x - bf_lo_f32(ah3), v3.y - bf_hi_f32(ah3));
                #pragma unroll
                for (int nt = 0; nt < 4; nt++) {
                    const u64* wb = sP1 + ((nt * 4 + kt) * 2) * 32 + lane_off;
                    u64 w0 = wb[0], w1 = wb[32];
                    u32 b0h = (u32)w0, b0l = (u32)(w0 >> 32);
                    u32 b1h = (u32)w1, b1l = (u32)(w1 >> 32);
                    mma_bf16(C[nt], ah0, ah1, ah2, ah3, b0h, b1h);
                    mma_bf16(C[nt], al0, al1, al2, al3, b0h, b1h);
                    mma_bf16(C[nt], ah0, ah1, ah2, ah3, b0l, b1l);
                }
            }
            float accLo = 0.f, accHi = 0.f;
            #pragma unroll
            for (int nt = 0; nt < 4; nt++) {
                int col = nt * 8 + 2 * tt;
                float w0 = sm[OFF_P2 + col], w1 = sm[OFF_P2 + col + 1];
                accLo += fmaxf(C[nt][0], 0.f) * w0 + fmaxf(C[nt][1], 0.f) * w1;
                accHi += fmaxf(C[nt][2], 0.f) * w0 + fmaxf(C[nt][3], 0.f) * w1;
            }
            accLo += __shfl_xor_sync(0xffffffffu, accLo, 1);
            accLo += __shfl_xor_sync(0xffffffffu, accLo, 2);
            accHi += __shfl_xor_sync(0xffffffffu, accHi, 1);
            accHi += __shfl_xor_sync(0xffffffffu, accHi, 2);
            float pb2v = sm[OFF_PB2];
            if (wiq == 0 && tt == 0) {
                if (v_lo) out[(size_t)n1 * OUTW + 67] =
                    1.f / (1.f + expf(-(accLo + pb2v)));
                if (v_hi) out[(size_t)n2 * OUTW + 67] =
                    1.f / (1.f + expf(-(accHi + pb2v)));
            }
            QUAD_BAR();   // all warps done reading Abuf before next group
        }
    }
    #undef QUAD_BAR
}

// ---------------------------------------------------------------------------
extern "C" void kernel_launch(void* const* d_in, const int* in_sizes, int n_in,
                              void* d_out, int out_size) {
    const float* nf  = (const float*)d_in[0];
    const float* ops = (const float*)d_in[1];
    const int*   ei  = (const int*)d_in[2];
    const float* W1  = (const float*)d_in[3];
    const float* b1  = (const float*)d_in[4];
    const float* W2  = (const float*)d_in[5];
    const float* b2  = (const float*)d_in[6];
    const float* W3  = (const float*)d_in[7];
    const float* b3  = (const float*)d_in[8];
    const float* P1  = (const float*)d_in[9];
    const float* pb1 = (const float*)d_in[10];
    const float* P2  = (const float*)d_in[11];
    const float* pb2 = (const float*)d_in[12];
    float* out = (float*)d_out;

    int E = in_sizes[2] / 2;

    pmask_kernel<<<(N_NODES + 255) / 256, 256>>>(ops, out);

    edge_kernel<<<(E + 255) / 256, 256>>>(ei, (const float4*)nf, E);

    compact_kernel<<<(N_NODES + 255) / 256, 256>>>(out);

    static_assert(SMEM_FLOATS * 4 <= 227 * 1024, "smem");
    cudaFuncSetAttribute(mlp_kernel,
                         cudaFuncAttributeMaxDynamicSharedMemorySize,
                         SMEM_FLOATS * 4);
    mlp_kernel<<<152, MTHREADS, SMEM_FLOATS * 4>>>(
        nf, W1, b1, W2, b2, W3, b3, P1, pb1, P2, pb2, out);
}

// round 17
// speedup vs baseline: 1.1637x; 1.1637x over previous
#include <cuda_runtime.h>
#include <cstdint>

#define N_NODES 100000
#define OUTW 68
typedef unsigned long long u64;
typedef unsigned int u32;

__device__ float g_nsum[(size_t)N_NODES * 64];
__device__ float g_deg[N_NODES];
__device__ unsigned g_pmaskbits[3136];
__device__ int g_list[N_NODES];
__device__ int g_cnt;

// ---------------------------------------------------------------------------
// helpers
// ---------------------------------------------------------------------------
__device__ __forceinline__ u32 pack_bf16x2(float x0, float x1) {
    u32 r;
    asm("{.reg .b16 lo, hi;\n\t"
        "cvt.rn.bf16.f32 lo, %1;\n\t"
        "cvt.rn.bf16.f32 hi, %2;\n\t"
        "mov.b32 %0, {lo, hi};}"
        : "=r"(r) : "f"(x0), "f"(x1));
    return r;
}
__device__ __forceinline__ float bf_lo_f32(u32 w) { return __uint_as_float(w << 16); }
__device__ __forceinline__ float bf_hi_f32(u32 w) { return __uint_as_float(w & 0xffff0000u); }

__device__ __forceinline__ void mma_bf16(float* c, u32 a0, u32 a1, u32 a2, u32 a3,
                                         u32 b0, u32 b1) {
    asm("mma.sync.aligned.m16n8k16.row.col.f32.bf16.bf16.f32 "
        "{%0,%1,%2,%3}, {%4,%5,%6,%7}, {%8,%9}, {%0,%1,%2,%3};"
        : "+f"(c[0]), "+f"(c[1]), "+f"(c[2]), "+f"(c[3])
        : "r"(a0), "r"(a1), "r"(a2), "r"(a3), "r"(b0), "r"(b1));
}

// ---------------------------------------------------------------------------
// Kernel 1: softmax gate -> bit mask, zero deg, zero nsum rows of gate-pass
// nodes. (Gate-fail output zeroing moved into edge_kernel.)
// ---------------------------------------------------------------------------
__global__ void pmask_kernel(const float* __restrict__ ops) {
    int n = blockIdx.x * blockDim.x + threadIdx.x;
    if (n == 0) g_cnt = 0;
    bool msk = false;
    if (n < N_NODES) {
        float o0 = ops[n * 4 + 0], o1 = ops[n * 4 + 1];
        float o2 = ops[n * 4 + 2], o3 = ops[n * 4 + 3];
        float mx = fmaxf(fmaxf(o0, o1), fmaxf(o2, o3));
        float e0 = expf(o0 - mx), e1 = expf(o1 - mx);
        float e2 = expf(o2 - mx), e3 = expf(o3 - mx);
        float p0 = e0 / (e0 + e1 + e2 + e3);
        msk = (p0 > 0.5f);
        g_deg[n] = 0.f;
    }
    unsigned bits = __ballot_sync(0xffffffffu, msk);
    if ((threadIdx.x & 31) == 0 && (n & ~31) < N_NODES)
        g_pmaskbits[n >> 5] = bits;
    if (msk) {
        float4 z = make_float4(0.f, 0.f, 0.f, 0.f);
        float4* row = reinterpret_cast<float4*>(g_nsum) + (size_t)n * 16;
        #pragma unroll
        for (int c = 0; c < 16; c++) row[c] = z;
    }
}

// ---------------------------------------------------------------------------
// Kernel 2: gated edge scatter (one thread/edge, ballot redistribution) PLUS
// gate-fail output zeroing as a per-thread side job: edge's L2-bound scatter
// overlaps with these DRAM-bound streaming stores.
// ---------------------------------------------------------------------------
__device__ __forceinline__ void scatter_jobs(bool active, int tgt, int srcn,
                                             int lane,
                                             const float4* __restrict__ feat4,
                                             float4* nsum4) {
    unsigned m = __ballot_sync(0xffffffffu, active);
    int grp = lane >> 3;
    int c = lane & 7;
    while (m) {
        int b0 = -1, b1 = -1, b2 = -1, b3 = -1;
        b0 = __ffs(m) - 1; m &= m - 1;
        if (m) { b1 = __ffs(m) - 1; m &= m - 1; }
        if (m) { b2 = __ffs(m) - 1; m &= m - 1; }
        if (m) { b3 = __ffs(m) - 1; m &= m - 1; }
        int myb = (grp == 0) ? b0 : (grp == 1) ? b1 : (grp == 2) ? b2 : b3;
        int bb = (myb >= 0) ? myb : b0;
        int T = __shfl_sync(0xffffffffu, tgt,  bb);
        int S = __shfl_sync(0xffffffffu, srcn, bb);
        if (myb >= 0) {
            float4 v0 = __ldg(&feat4[(size_t)S * 16 + c]);
            float4 v1 = __ldg(&feat4[(size_t)S * 16 + c + 8]);
            asm volatile("red.global.add.v4.f32 [%0], {%1,%2,%3,%4};" ::
                         "l"(nsum4 + (size_t)T * 16 + c),
                         "f"(v0.x), "f"(v0.y), "f"(v0.z), "f"(v0.w) : "memory");
            asm volatile("red.global.add.v4.f32 [%0], {%1,%2,%3,%4};" ::
                         "l"(nsum4 + (size_t)T * 16 + c + 8),
                         "f"(v1.x), "f"(v1.y), "f"(v1.z), "f"(v1.w) : "memory");
            if (c == 0) atomicAdd(&g_deg[T], 1.f);
        }
    }
}

__global__ void edge_kernel(const int* __restrict__ ei,
                            const float4* __restrict__ feat4,
                            int E,
                            float* __restrict__ out) {
    int t = blockIdx.x * blockDim.x + threadIdx.x;
    int lane = threadIdx.x & 31;

    // ---- side job: zero output rows of gate-fail nodes (1 float4/thread) ----
    if (t < N_NODES * 17) {
        int row = t / 17;
        int c   = t - row * 17;
        if (!((g_pmaskbits[row >> 5] >> (row & 31)) & 1)) {
            float4* p = reinterpret_cast<float4*>(out) + (size_t)row * 17 + c;
            asm volatile("st.global.cs.v4.f32 [%0], {%1,%1,%1,%1};" ::
                         "l"(p), "f"(0.f) : "memory");
        }
    }

    // ---- main job: gated scatter ----
    int e = t;
    bool v = e < E;
    int s = 0, d = 0;
    if (v) { s = __ldg(&ei[e]); d = __ldg(&ei[E + e]); }
    bool a0 = v && ((g_pmaskbits[s >> 5] >> (s & 31)) & 1);
    bool a1 = v && ((g_pmaskbits[d >> 5] >> (d & 31)) & 1);
    float4* nsum4 = reinterpret_cast<float4*>(g_nsum);
    scatter_jobs(a0, s, d, lane, feat4, nsum4);
    scatter_jobs(a1, d, s, lane, feat4, nsum4);
}

// ---------------------------------------------------------------------------
// Kernel 3: compact active nodes; zero output rows of gate-pass-but-deg0 nodes
// ---------------------------------------------------------------------------
__global__ void compact_kernel(float* __restrict__ out) {
    int n = blockIdx.x * blockDim.x + threadIdx.x;
    int lane = threadIdx.x & 31;
    bool gate = false, act = false;
    if (n < N_NODES) {
        gate = (g_pmaskbits[n >> 5] >> (n & 31)) & 1;
        act = gate && (g_deg[n] > 0.f);
    }
    unsigned m = __ballot_sync(0xffffffffu, act);
    int base = 0;
    if (lane == 0 && m) base = atomicAdd(&g_cnt, __popc(m));
    base = __shfl_sync(0xffffffffu, base, 0);
    if (act) g_list[base + __popc(m & ((1u << lane) - 1))] = n;
    if (gate && !act) {
        float4 z = make_float4(0.f, 0.f, 0.f, 0.f);
        float4* orow = reinterpret_cast<float4*>(out + (size_t)n * OUTW);
        #pragma unroll
        for (int c = 0; c < 17; c++) orow[c] = z;
    }
}

// ---------------------------------------------------------------------------
// Kernel 4: tensor-core MLP, QUAD warps; 24 warps/block = 6 quads (R15 core)
// ---------------------------------------------------------------------------
#define MWARPS 24
#define QUADS  (MWARPS / 4)
#define MTHREADS (MWARPS * 32)
#define SA 132

#define OFF_W1B  0          // 8192 u64
#define OFF_W2B  16384      // 4096 u64
#define OFF_W3B  24576      // 2304 u64
#define OFF_P1B  29184      // 1024 u64
#define OFF_B1   31232
#define OFF_B2   31360
#define OFF_B3   31424      // 72
#define OFF_PB1  31496
#define OFF_P2   31528
#define OFF_PB2  31560
#define OFF_ABUF 31562
#define SMEM_FLOATS (OFF_ABUF + QUADS * 16 * SA)

__device__ void stage_wfrag(const float* __restrict__ W, u64* dst,
                            int KT, int NT, int Kv, int Nv, int ld, int tid) {
    int total = NT * KT * 64;
    for (int idx = tid; idx < total; idx += MTHREADS) {
        int gg  = idx & 7;
        int tt  = (idx >> 3) & 3;
        int reg = (idx >> 5) & 1;
        int kt  = (idx >> 6) % KT;
        int nt  = (idx >> 6) / KT;
        int k0 = kt * 16 + reg * 8 + 2 * tt;
        int n  = nt * 8 + gg;
        float w0 = (k0 < Kv && n < Nv) ? W[k0 * ld + n] : 0.f;
        float w1 = (k0 + 1 < Kv && n < Nv) ? W[(k0 + 1) * ld + n] : 0.f;
        u32 hi = pack_bf16x2(w0, w1);
        u32 lo = pack_bf16x2(w0 - bf_lo_f32(hi), w1 - bf_hi_f32(hi));
        dst[idx] = (u64)hi | ((u64)lo << 32);
    }
}

__global__ void __launch_bounds__(MTHREADS, 1)
mlp_kernel(const float* __restrict__ nf,
           const float* __restrict__ W1, const float* __restrict__ b1,
           const float* __restrict__ W2, const float* __restrict__ b2,
           const float* __restrict__ W3, const float* __restrict__ b3,
           const float* __restrict__ P1, const float* __restrict__ pb1,
           const float* __restrict__ P2, const float* __restrict__ pb2,
           float* __restrict__ out) {
    extern __shared__ float sm[];
    const int tid = threadIdx.x;

    stage_wfrag(W1, reinterpret_cast<u64*>(sm + OFF_W1B), 8, 16, 128, 128, 128, tid);
    stage_wfrag(W2, reinterpret_cast<u64*>(sm + OFF_W2B), 8,  8, 128,  64,  64, tid);
    stage_wfrag(W3, reinterpret_cast<u64*>(sm + OFF_W3B), 4,  9,  64,  67,  67, tid);
    stage_wfrag(P1, reinterpret_cast<u64*>(sm + OFF_P1B), 4,  4,  64,  32,  32, tid);
    for (int i = tid; i < 128; i += MTHREADS) sm[OFF_B1 + i] = b1[i];
    for (int i = tid; i < 64;  i += MTHREADS) sm[OFF_B2 + i] = b2[i];
    for (int i = tid; i < 72;  i += MTHREADS) sm[OFF_B3 + i] = (i < 67) ? b3[i] : 0.f;
    for (int i = tid; i < 32;  i += MTHREADS) sm[OFF_PB1 + i] = pb1[i];
    for (int i = tid; i < 32;  i += MTHREADS) sm[OFF_P2 + i] = P2[i];
    if (tid == 0) sm[OFF_PB2] = pb2[0];
    __syncthreads();

    const int warpId = tid >> 5;
    const int quadId = warpId >> 2;
    const int wiq    = warpId & 3;
    const int lane = tid & 31;
    const int tt = lane & 3;
    const int gg = lane >> 2;
    const int lane_off = tt * 8 + gg;

    #define QUAD_BAR() asm volatile("bar.sync %0, 128;" :: "r"(quadId + 1) : "memory")

    float* Abuf = sm + OFF_ABUF + quadId * (16 * SA);
    const u64* sW1 = reinterpret_cast<const u64*>(sm + OFF_W1B);
    const u64* sW2 = reinterpret_cast<const u64*>(sm + OFF_W2B);
    const u64* sW3 = reinterpret_cast<const u64*>(sm + OFF_W3B);
    const u64* sP1 = reinterpret_cast<const u64*>(sm + OFF_P1B);

    const int cnt = g_cnt;
    const int totalQuads = gridDim.x * QUADS;

    for (int grp = blockIdx.x * QUADS + quadId; grp * 16 < cnt; grp += totalQuads) {
        const int gbase = grp * 16;

        int li_lo = gbase + gg;
        int li_hi = gbase + gg + 8;
        bool v_lo = li_lo < cnt;
        bool v_hi = li_hi < cnt;
        int n1 = g_list[v_lo ? li_lo : gbase];
        int n2 = g_list[v_hi ? li_hi : gbase];

        // ---- ctx load: each warp loads 4 of the 16 rows ----
        #pragma unroll
        for (int j = 0; j < 4; j++) {
            int q = wiq * 4 + j;
            int li = gbase + q;
            int nq = g_list[(li < cnt) ? li : gbase];
            float inv = 1.f / fmaxf(g_deg[nq], 1.f);
            Abuf[q * SA + lane]      = nf[(size_t)nq * 64 + lane];
            Abuf[q * SA + 32 + lane] = nf[(size_t)nq * 64 + 32 + lane];
            Abuf[q * SA + 64 + lane] = g_nsum[(size_t)nq * 64 + lane] * inv;
            Abuf[q * SA + 96 + lane] = g_nsum[(size_t)nq * 64 + 32 + lane] * inv;
        }
        QUAD_BAR();

        // ================= layer 1: warp does nt = wiq*4 .. +3 ============
        {
            const int ntBase = wiq * 4;
            float C[4][4];
            #pragma unroll
            for (int j = 0; j < 4; j++) {
                int nt = ntBase + j;
                float bb0 = sm[OFF_B1 + nt * 8 + 2 * tt];
                float bb1 = sm[OFF_B1 + nt * 8 + 2 * tt + 1];
                C[j][0] = bb0; C[j][1] = bb1; C[j][2] = bb0; C[j][3] = bb1;
            }
            #pragma unroll
            for (int kt = 0; kt < 8; kt++) {
                float2 v0 = *reinterpret_cast<float2*>(&Abuf[gg * SA + kt * 16 + 2 * tt]);
                float2 v1 = *reinterpret_cast<float2*>(&Abuf[(gg + 8) * SA + kt * 16 + 2 * tt]);
                float2 v2 = *reinterpret_cast<float2*>(&Abuf[gg * SA + kt * 16 + 8 + 2 * tt]);
                float2 v3 = *reinterpret_cast<float2*>(&Abuf[(gg + 8) * SA + kt * 16 + 8 + 2 * tt]);
                u32 ah0 = pack_bf16x2(v0.x, v0.y), ah1 = pack_bf16x2(v1.x, v1.y);
                u32 ah2 = pack_bf16x2(v2.x, v2.y), ah3 = pack_bf16x2(v3.x, v3.y);
                u32 al0 = pack_bf16x2(v0.x - bf_lo_f32(ah0), v0.y - bf_hi_f32(ah0));
                u32 al1 = pack_bf16x2(v1.x - bf_lo_f32(ah1), v1.y - bf_hi_f32(ah1));
                u32 al2 = pack_bf16x2(v2.x - bf_lo_f32(ah2), v2.y - bf_hi_f32(ah2));
                u32 al3 = pack_bf16x2(v3.x - bf_lo_f32(ah3), v3.y - bf_hi_f32(ah3));
                #pragma unroll
                for (int j = 0; j < 4; j++) {
                    int nt = ntBase + j;
                    const u64* wb = sW1 + ((nt * 8 + kt) * 2) * 32 + lane_off;
                    u64 w0 = wb[0], w1 = wb[32];
                    u32 b0h = (u32)w0, b0l = (u32)(w0 >> 32);
                    u32 b1h = (u32)w1, b1l = (u32)(w1 >> 32);
                    mma_bf16(C[j], ah0, ah1, ah2, ah3, b0h, b1h);
                    mma_bf16(C[j], al0, al1, al2, al3, b0h, b1h);
                    mma_bf16(C[j], ah0, ah1, ah2, ah3, b0l, b1l);
                }
            }
            QUAD_BAR();   // done READING Abuf before overwrite
            #pragma unroll
            for (int j = 0; j < 4; j++) {
                int nt = ntBase + j;
                *reinterpret_cast<float2*>(&Abuf[gg * SA + nt * 8 + 2 * tt]) =
                    make_float2(fmaxf(C[j][0], 0.f), fmaxf(C[j][1], 0.f));
                *reinterpret_cast<float2*>(&Abuf[(gg + 8) * SA + nt * 8 + 2 * tt]) =
                    make_float2(fmaxf(C[j][2], 0.f), fmaxf(C[j][3], 0.f));
            }
            QUAD_BAR();
        }

        // ================= layer 2: warp does nt = wiq*2 .. +1 ============
        {
            const int ntBase = wiq * 2;
            float C[2][4];
            #pragma unroll
            for (int j = 0; j < 2; j++) {
                int nt = ntBase + j;
                float bb0 = sm[OFF_B2 + nt * 8 + 2 * tt];
                float bb1 = sm[OFF_B2 + nt * 8 + 2 * tt + 1];
                C[j][0] = bb0; C[j][1] = bb1; C[j][2] = bb0; C[j][3] = bb1;
            }
            #pragma unroll
            for (int kt = 0; kt < 8; kt++) {
                float2 v0 = *reinterpret_cast<float2*>(&Abuf[gg * SA + kt * 16 + 2 * tt]);
                float2 v1 = *reinterpret_cast<float2*>(&Abuf[(gg + 8) * SA + kt * 16 + 2 * tt]);
                float2 v2 = *reinterpret_cast<float2*>(&Abuf[gg * SA + kt * 16 + 8 + 2 * tt]);
                float2 v3 = *reinterpret_cast<float2*>(&Abuf[(gg + 8) * SA + kt * 16 + 8 + 2 * tt]);
                u32 ah0 = pack_bf16x2(v0.x, v0.y), ah1 = pack_bf16x2(v1.x, v1.y);
                u32 ah2 = pack_bf16x2(v2.x, v2.y), ah3 = pack_bf16x2(v3.x, v3.y);
                u32 al0 = pack_bf16x2(v0.x - bf_lo_f32(ah0), v0.y - bf_hi_f32(ah0));
                u32 al1 = pack_bf16x2(v1.x - bf_lo_f32(ah1), v1.y - bf_hi_f32(ah1));
                u32 al2 = pack_bf16x2(v2.x - bf_lo_f32(ah2), v2.y - bf_hi_f32(ah2));
                u32 al3 = pack_bf16x2(v3.x - bf_lo_f32(ah3), v3.y - bf_hi_f32(ah3));
                #pragma unroll
                for (int j = 0; j < 2; j++) {
                    int nt = ntBase + j;
                    const u64* wb = sW2 + ((nt * 8 + kt) * 2) * 32 + lane_off;
                    u64 w0 = wb[0], w1 = wb[32];
                    u32 b0h = (u32)w0, b0l = (u32)(w0 >> 32);
                    u32 b1h = (u32)w1, b1l = (u32)(w1 >> 32);
                    mma_bf16(C[j], ah0, ah1, ah2, ah3, b0h, b1h);
                    mma_bf16(C[j], al0, al1, al2, al3, b0h, b1h);
                    mma_bf16(C[j], ah0, ah1, ah2, ah3, b0l, b1l);
                }
            }
            QUAD_BAR();
            #pragma unroll
            for (int j = 0; j < 2; j++) {
                int nt = ntBase + j;
                *reinterpret_cast<float2*>(&Abuf[gg * SA + nt * 8 + 2 * tt]) =
                    make_float2(fmaxf(C[j][0], 0.f), fmaxf(C[j][1], 0.f));
                *reinterpret_cast<float2*>(&Abuf[(gg + 8) * SA + nt * 8 + 2 * tt]) =
                    make_float2(fmaxf(C[j][2], 0.f), fmaxf(C[j][3], 0.f));
            }
            QUAD_BAR();
        }

        // ================= layer 3: 9 nt tiles, split 3/2/2/2 ==============
        {
            const int l3base = (wiq == 0) ? 0 : (wiq == 1) ? 3 : (wiq == 2) ? 5 : 7;
            const int l3cnt  = (wiq == 0) ? 3 : 2;
            float C[3][4];
            #pragma unroll
            for (int j = 0; j < 3; j++) {
                if (j >= l3cnt) break;
                int nt = l3base + j;
                float bb0 = sm[OFF_B3 + nt * 8 + 2 * tt];
                float bb1 = sm[OFF_B3 + nt * 8 + 2 * tt + 1];
                C[j][0] = bb0; C[j][1] = bb1; C[j][2] = bb0; C[j][3] = bb1;
            }
            #pragma unroll
            for (int kt = 0; kt < 4; kt++) {
                float2 v0 = *reinterpret_cast<float2*>(&Abuf[gg * SA + kt * 16 + 2 * tt]);
                float2 v1 = *reinterpret_cast<float2*>(&Abuf[(gg + 8) * SA + kt * 16 + 2 * tt]);
                float2 v2 = *reinterpret_cast<float2*>(&Abuf[gg * SA + kt * 16 + 8 + 2 * tt]);
                float2 v3 = *reinterpret_cast<float2*>(&Abuf[(gg + 8) * SA + kt * 16 + 8 + 2 * tt]);
                u32 ah0 = pack_bf16x2(v0.x, v0.y), ah1 = pack_bf16x2(v1.x, v1.y);
                u32 ah2 = pack_bf16x2(v2.x, v2.y), ah3 = pack_bf16x2(v3.x, v3.y);
                u32 al0 = pack_bf16x2(v0.x - bf_lo_f32(ah0), v0.y - bf_hi_f32(ah0));
                u32 al1 = pack_bf16x2(v1.x - bf_lo_f32(ah1), v1.y - bf_hi_f32(ah1));
                u32 al2 = pack_bf16x2(v2.x - bf_lo_f32(ah2), v2.y - bf_hi_f32(ah2));
                u32 al3 = pack_bf16x2(v3.x - bf_lo_f32(ah3), v3.y - bf_hi_f32(ah3));
                #pragma unroll
                for (int j = 0; j < 3; j++) {
                    if (j >= l3cnt) break;
                    int nt = l3base + j;
                    const u64* wb = sW3 + ((nt * 4 + kt) * 2) * 32 + lane_off;
                    u64 w0 = wb[0], w1 = wb[32];
                    u32 b0h = (u32)w0, b0l = (u32)(w0 >> 32);
                    u32 b1h = (u32)w1, b1l = (u32)(w1 >> 32);
                    mma_bf16(C[j], ah0, ah1, ah2, ah3, b0h, b1h);
                    mma_bf16(C[j], al0, al1, al2, al3, b0h, b1h);
                    mma_bf16(C[j], ah0, ah1, ah2, ah3, b0l, b1l);
                }
            }
            QUAD_BAR();
            #pragma unroll
            for (int j = 0; j < 3; j++) {
                if (j >= l3cnt) break;
                int nt = l3base + j;
                int col = nt * 8 + 2 * tt;
                float r0 = C[j][0], r1 = C[j][1], r2 = C[j][2], r3 = C[j][3];
                if (col < 67) {
                    if (v_lo) out[(size_t)n1 * OUTW + col] = r0;
                    if (v_hi) out[(size_t)n2 * OUTW + col] = r2;
                    if (col >= 3) {
                        Abuf[gg * SA + col - 3] = r0;
                        Abuf[(gg + 8) * SA + col - 3] = r2;
                    }
                }
                if (col + 1 < 67) {
                    if (v_lo) out[(size_t)n1 * OUTW + col + 1] = r1;
                    if (v_hi) out[(size_t)n2 * OUTW + col + 1] = r3;
                    if (col + 1 >= 3) {
                        Abuf[gg * SA + col - 2] = r1;
                        Abuf[(gg + 8) * SA + col - 2] = r3;
                    }
                }
            }
            QUAD_BAR();
        }

        // ================= head (duplicated in all warps, wiq0 writes) =====
        {
            float C[4][4];
            #pragma unroll
            for (int nt = 0; nt < 4; nt++) {
                float bb0 = sm[OFF_PB1 + nt * 8 + 2 * tt];
                float bb1 = sm[OFF_PB1 + nt * 8 + 2 * tt + 1];
                C[nt][0] = bb0; C[nt][1] = bb1; C[nt][2] = bb0; C[nt][3] = bb1;
            }
            #pragma unroll
            for (int kt = 0; kt < 4; kt++) {
                float2 v0 = *reinterpret_cast<float2*>(&Abuf[gg * SA + kt * 16 + 2 * tt]);
                float2 v1 = *reinterpret_cast<float2*>(&Abuf[(gg + 8) * SA + kt * 16 + 2 * tt]);
                float2 v2 = *reinterpret_cast<float2*>(&Abuf[gg * SA + kt * 16 + 8 + 2 * tt]);
                float2 v3 = *reinterpret_cast<float2*>(&Abuf[(gg + 8) * SA + kt * 16 + 8 + 2 * tt]);
                u32 ah0 = pack_bf16x2(v0.x, v0.y), ah1 = pack_bf16x2(v1.x, v1.y);
                u32 ah2 = pack_bf16x2(v2.x, v2.y), ah3 = pack_bf16x2(v3.x, v3.y);
                u32 al0 = pack_bf16x2(v0.x - bf_lo_f32(ah0), v0.y - bf_hi_f32(ah0));
                u32 al1 = pack_bf16x2(v1.x - bf_lo_f32(ah1), v1.y - bf_hi_f32(ah1));
                u32 al2 = pack_bf16x2(v2.x - bf_lo_f32(ah2), v2.y - bf_hi_f32(ah2));
                u32 al3 = pack_bf16x2(v3.x - bf_lo_f32(ah3), v3.y - bf_hi_f32(ah3));
                #pragma unroll
                for (int nt = 0; nt < 4; nt++) {
                    const u64* wb = sP1 + ((nt * 4 + kt) * 2) * 32 + lane_off;
                    u64 w0 = wb[0], w1 = wb[32];
                    u32 b0h = (u32)w0, b0l = (u32)(w0 >> 32);
                    u32 b1h = (u32)w1, b1l = (u32)(w1 >> 32);
                    mma_bf16(C[nt], ah0, ah1, ah2, ah3, b0h, b1h);
                    mma_bf16(C[nt], al0, al1, al2, al3, b0h, b1h);
                    mma_bf16(C[nt], ah0, ah1, ah2, ah3, b0l, b1l);
                }
            }
            float accLo = 0.f, accHi = 0.f;
            #pragma unroll
            for (int nt = 0; nt < 4; nt++) {
                int col = nt * 8 + 2 * tt;
                float w0 = sm[OFF_P2 + col], w1 = sm[OFF_P2 + col + 1];
                accLo += fmaxf(C[nt][0], 0.f) * w0 + fmaxf(C[nt][1], 0.f) * w1;
                accHi += fmaxf(C[nt][2], 0.f) * w0 + fmaxf(C[nt][3], 0.f) * w1;
            }
            accLo += __shfl_xor_sync(0xffffffffu, accLo, 1);
            accLo += __shfl_xor_sync(0xffffffffu, accLo, 2);
            accHi += __shfl_xor_sync(0xffffffffu, accHi, 1);
            accHi += __shfl_xor_sync(0xffffffffu, accHi, 2);
            float pb2v = sm[OFF_PB2];
            if (wiq == 0 && tt == 0) {
                if (v_lo) out[(size_t)n1 * OUTW + 67] =
                    1.f / (1.f + expf(-(accLo + pb2v)));
                if (v_hi) out[(size_t)n2 * OUTW + 67] =
                    1.f / (1.f + expf(-(accHi + pb2v)));
            }
            QUAD_BAR();   // all warps done reading Abuf before next group
        }
    }
    #undef QUAD_BAR
}

// ---------------------------------------------------------------------------
extern "C" void kernel_launch(void* const* d_in, const int* in_sizes, int n_in,
                              void* d_out, int out_size) {
    const float* nf  = (const float*)d_in[0];
    const float* ops = (const float*)d_in[1];
    const int*   ei  = (const int*)d_in[2];
    const float* W1  = (const float*)d_in[3];
    const float* b1  = (const float*)d_in[4];
    const float* W2  = (const float*)d_in[5];
    const float* b2  = (const float*)d_in[6];
    const float* W3  = (const float*)d_in[7];
    const float* b3  = (const float*)d_in[8];
    const float* P1  = (const float*)d_in[9];
    const float* pb1 = (const float*)d_in[10];
    const float* P2  = (const float*)d_in[11];
    const float* pb2 = (const float*)d_in[12];
    float* out = (float*)d_out;

    int E = in_sizes[2] / 2;

    pmask_kernel<<<(N_NODES + 255) / 256, 256>>>(ops);

    // edge grid must cover max(E, N_NODES*17) threads for the zeroing side job
    int ethreads = (E > N_NODES * 17) ? E : N_NODES * 17;
    edge_kernel<<<(ethreads + 255) / 256, 256>>>(ei, (const float4*)nf, E, out);

    compact_kernel<<<(N_NODES + 255) / 256, 256>>>(out);

    static_assert(SMEM_FLOATS * 4 <= 227 * 1024, "smem");
    cudaFuncSetAttribute(mlp_kernel,
                         cudaFuncAttributeMaxDynamicSharedMemorySize,
                         SMEM_FLOATS * 4);
    mlp_kernel<<<152, MTHREADS, SMEM_FLOATS * 4>>>(
        nf, W1, b1, W2, b2, W3, b3, P1, pb1, P2, pb2, out);
}